// round 8
// baseline (speedup 1.0000x reference)
#include <cuda_runtime.h>
#include <cuda_bf16.h>

// Problem shape (fixed by setup_inputs): B=8, H=96, W=256
// corr_i: (N, 1, 1, W>>i) fp32, flow: (B, 2, H, W) fp32
// out: (B, 4*K, H, W) fp32 with K = 9 taps (R = 4)
//
// Strategy: each pixel's 9 taps per level read the contiguous 10-float window
// [base, base+9], base = floor(d) - R, shared weight w = d - floor(d).
// Load the ALIGNED 16-float superset starting at s = base & ~3 as four
// predicated float4s (each float4 is wholly in- or out-of-row since Wi and s
// are multiples of 4; OOB quarters = 0, matching zero padding). Resolve the
// residual shift o = base & 3 with a static select tree (no dynamic reg
// indexing, no clamping edge cases). 4 LDG.128/level vs 10 LDG.32 -> 2.5x
// fewer L1 sector-wavefronts per pixel (lanes hit disjoint rows, so every
// lane-sector is a separate wavefront).

namespace {

constexpr int Hsz = 96;
constexpr int Wsz = 256;
constexpr int HW  = Hsz * Wsz;          // 24576
constexpr int N   = 8 * HW;             // 196608
constexpr int R   = 4;
constexpr int K   = 2 * R + 1;          // 9
constexpr int C   = 4 * K;              // 36 output channels

__device__ __forceinline__ void load_level(
    const float* __restrict__ row, int Wi, float d,
    float& wgt, int& o, float (&X)[16])
{
    float fd = floorf(d);
    wgt = d - fd;
    int base = (int)fd - R;             // in [-R, Wi-R-1]
    int s = base & ~3;                  // aligned superset start (may be <0)
    o = base & 3;
    const float4* r4 = (const float4*)row;   // rows are >=128B aligned
#pragma unroll
    for (int j = 0; j < 4; ++j) {
        int e = s + 4 * j;
        float4 q = make_float4(0.f, 0.f, 0.f, 0.f);
        if (e >= 0 && e < Wi) q = __ldcs(r4 + (e >> 2));
        X[4 * j + 0] = q.x; X[4 * j + 1] = q.y;
        X[4 * j + 2] = q.z; X[4 * j + 3] = q.w;
    }
}

__device__ __forceinline__ void emit_level(
    const float (&X)[16], int o, float w, float* __restrict__ outp)
{
    bool o1 = (o & 1) != 0;
    bool o2 = (o & 2) != 0;
    // xs[m] = X[o + m], m = 0..10, via 2-level static select (o in 0..3;
    // max index o+10 <= 13 < 16).
    float xs[11];
#pragma unroll
    for (int m = 0; m < 11; ++m) {
        float a = o1 ? X[m + 1] : X[m + 0];
        float b = o1 ? X[m + 3] : X[m + 2];
        xs[m] = o2 ? b : a;
    }
    float omw = 1.0f - w;
#pragma unroll
    for (int k = 0; k < K; ++k)
        __stcs(outp + k * HW, omw * xs[k] + w * xs[k + 1]);
}

__global__ void __launch_bounds__(64, 21)
corr_lookup_kernel(const float* __restrict__ c0,
                   const float* __restrict__ c1,
                   const float* __restrict__ c2,
                   const float* __restrict__ c3,
                   const float* __restrict__ flow,
                   float* __restrict__ out)
{
    int n = blockIdx.x * blockDim.x + threadIdx.x;
    if (n >= N) return;

    int b = n / HW;
    int r = n - b * HW;                  // h*W + w within the image

    float disp = __ldg(flow + (size_t)b * 2 * HW + r);
    float* outp = out + (size_t)b * C * HW + r;

    // Pair 1: levels 0 and 1 (loads front-batched, 8 LDG.128 in flight)
    {
        float w0, w1; int o0, o1v; float X0[16], X1[16];
        load_level(c0 + (size_t)n * 256, 256, disp,        w0, o0,  X0);
        load_level(c1 + (size_t)n * 128, 128, disp * 0.5f, w1, o1v, X1);
        emit_level(X0, o0,  w0, outp + 0 * K * HW);
        emit_level(X1, o1v, w1, outp + 1 * K * HW);
    }
    // Pair 2: levels 2 and 3
    {
        float w2, w3; int o2v, o3v; float X2[16], X3[16];
        load_level(c2 + (size_t)n * 64, 64, disp * 0.25f,  w2, o2v, X2);
        load_level(c3 + (size_t)n * 32, 32, disp * 0.125f, w3, o3v, X3);
        emit_level(X2, o2v, w2, outp + 2 * K * HW);
        emit_level(X3, o3v, w3, outp + 3 * K * HW);
    }
}

} // namespace

extern "C" void kernel_launch(void* const* d_in, const int* in_sizes, int n_in,
                              void* d_out, int out_size)
{
    const float* c0   = (const float*)d_in[0];
    const float* c1   = (const float*)d_in[1];
    const float* c2   = (const float*)d_in[2];
    const float* c3   = (const float*)d_in[3];
    const float* flow = (const float*)d_in[4];
    float* out = (float*)d_out;

    constexpr int TPB = 64;
    int blocks = (N + TPB - 1) / TPB;   // 3072
    corr_lookup_kernel<<<blocks, TPB>>>(c0, c1, c2, c3, flow, out);
}

// round 10
// speedup vs baseline: 1.0676x; 1.0676x over previous
#include <cuda_runtime.h>
#include <cuda_bf16.h>

// Problem shape (fixed by setup_inputs): B=8, H=96, W=256
// corr_i: (N, 1, 1, W>>i) fp32, flow: (B, 2, H, W) fp32
// out: (B, 4*K, H, W) fp32 with K = 9 taps (R = 4)
//
// All 9 taps of a level share w = d - floor(d) and read the contiguous
// 10-float window V[base..base+9], base = floor(d) - R:
//   out_k = (1-w)*V[k] + w*V[k+1]
// Reads are compulsory random ~64B-granule transactions (each pixel owns its
// corr row; zero reuse) -> DRAM-efficiency-bound. This round keeps the best
// measured structure (scalar window loads batched per level-pair) and switches
// stores from streaming (__stcs) to write-back so L2 (126MB, output is 28MB)
// buffers the write stream instead of interleaving eager write bursts into
// the random-read stream.

namespace {

constexpr int Hsz = 96;
constexpr int Wsz = 256;
constexpr int HW  = Hsz * Wsz;          // 24576
constexpr int N   = 8 * HW;             // 196608
constexpr int R   = 4;
constexpr int K   = 2 * R + 1;          // 9
constexpr int C   = 4 * K;              // 36 output channels

__device__ __forceinline__ void process_pair(
    const float* __restrict__ rowA, int WiA, float dA,
    const float* __restrict__ rowB, int WiB, float dB,
    float* __restrict__ outp)            // channel-strided by HW; 2*K channels
{
    float fdA = floorf(dA), fdB = floorf(dB);
    float wA = dA - fdA,    wB = dB - fdB;
    int baseA = (int)fdA - R;
    int baseB = (int)fdB - R;

    // Front-batch both windows' loads (20 outstanding scalar LDGs).
    float va[K + 1], vb[K + 1];
#pragma unroll
    for (int j = 0; j <= K; ++j) {
        int ia = baseA + j;
        va[j] = (ia >= 0 && ia < WiA) ? __ldcs(rowA + ia) : 0.0f;
    }
#pragma unroll
    for (int j = 0; j <= K; ++j) {
        int ib = baseB + j;
        vb[j] = (ib >= 0 && ib < WiB) ? __ldcs(rowB + ib) : 0.0f;
    }

    float omwA = 1.0f - wA, omwB = 1.0f - wB;
#pragma unroll
    for (int k = 0; k < K; ++k)
        outp[k * HW] = omwA * va[k] + wA * va[k + 1];
#pragma unroll
    for (int k = 0; k < K; ++k)
        outp[(K + k) * HW] = omwB * vb[k] + wB * vb[k + 1];
}

__global__ void __launch_bounds__(128, 12)
corr_lookup_kernel(const float* __restrict__ c0,
                   const float* __restrict__ c1,
                   const float* __restrict__ c2,
                   const float* __restrict__ c3,
                   const float* __restrict__ flow,
                   float* __restrict__ out)
{
    // Grid exactly covers N (1536 * 128 == 196608): no bounds branch.
    int n = blockIdx.x * blockDim.x + threadIdx.x;

    int b = n / HW;
    int r = n - b * HW;                  // h*W + w within the image

    // flow channel 0 (disparity) for this pixel
    float disp = __ldg(flow + (size_t)b * 2 * HW + r);

    float* outp = out + (size_t)b * C * HW + r;

    process_pair(c0 + (size_t)n * 256, 256, disp,
                 c1 + (size_t)n * 128, 128, disp * 0.5f,
                 outp);
    process_pair(c2 + (size_t)n * 64,  64,  disp * 0.25f,
                 c3 + (size_t)n * 32,  32,  disp * 0.125f,
                 outp + 2 * K * HW);
}

} // namespace

extern "C" void kernel_launch(void* const* d_in, const int* in_sizes, int n_in,
                              void* d_out, int out_size)
{
    const float* c0   = (const float*)d_in[0];
    const float* c1   = (const float*)d_in[1];
    const float* c2   = (const float*)d_in[2];
    const float* c3   = (const float*)d_in[3];
    const float* flow = (const float*)d_in[4];
    float* out = (float*)d_out;

    constexpr int TPB = 128;
    int blocks = N / TPB;               // 1536, exact
    corr_lookup_kernel<<<blocks, TPB>>>(c0, c1, c2, c3, flow, out);
}

// round 11
// speedup vs baseline: 1.0714x; 1.0036x over previous
#include <cuda_runtime.h>
#include <cuda_bf16.h>

// Problem shape (fixed by setup_inputs): B=8, H=96, W=256
// corr_i: (N, 1, 1, W>>i) fp32, flow: (B, 2, H, W) fp32
// out: (B, 4*K, H, W) fp32 with K = 9 taps (R = 4)
//
// All 9 taps of a level share w = d - floor(d) and read the contiguous
// 10-float window V[base..base+9], base = floor(d) - R:
//   out_k = (1-w)*V[k] + w*V[k+1]
// The kernel is bound by compulsory random ~64B-granule DRAM reads (each
// pixel owns its corr row; zero reuse; sector count invariant to load width).
// Best measured structure: scalar window loads batched per level-pair,
// plain write-back stores (L2 absorbs the 28MB output; ~2% win vs __stcs).
// This round: TPB=64 -> grid 3072 -> 20/21 CTAs per SM (~5% wave imbalance
// vs ~10% at TPB=128), still one wave at 40 regs.

namespace {

constexpr int Hsz = 96;
constexpr int Wsz = 256;
constexpr int HW  = Hsz * Wsz;          // 24576
constexpr int N   = 8 * HW;             // 196608
constexpr int R   = 4;
constexpr int K   = 2 * R + 1;          // 9
constexpr int C   = 4 * K;              // 36 output channels

__device__ __forceinline__ void process_pair(
    const float* __restrict__ rowA, int WiA, float dA,
    const float* __restrict__ rowB, int WiB, float dB,
    float* __restrict__ outp)            // channel-strided by HW; 2*K channels
{
    float fdA = floorf(dA), fdB = floorf(dB);
    float wA = dA - fdA,    wB = dB - fdB;
    int baseA = (int)fdA - R;
    int baseB = (int)fdB - R;

    // Front-batch both windows' loads (20 outstanding scalar LDGs).
    float va[K + 1], vb[K + 1];
#pragma unroll
    for (int j = 0; j <= K; ++j) {
        int ia = baseA + j;
        va[j] = (ia >= 0 && ia < WiA) ? __ldcs(rowA + ia) : 0.0f;
    }
#pragma unroll
    for (int j = 0; j <= K; ++j) {
        int ib = baseB + j;
        vb[j] = (ib >= 0 && ib < WiB) ? __ldcs(rowB + ib) : 0.0f;
    }

    float omwA = 1.0f - wA, omwB = 1.0f - wB;
#pragma unroll
    for (int k = 0; k < K; ++k)
        outp[k * HW] = omwA * va[k] + wA * va[k + 1];
#pragma unroll
    for (int k = 0; k < K; ++k)
        outp[(K + k) * HW] = omwB * vb[k] + wB * vb[k + 1];
}

__global__ void __launch_bounds__(64, 21)
corr_lookup_kernel(const float* __restrict__ c0,
                   const float* __restrict__ c1,
                   const float* __restrict__ c2,
                   const float* __restrict__ c3,
                   const float* __restrict__ flow,
                   float* __restrict__ out)
{
    // Grid exactly covers N (3072 * 64 == 196608): no bounds branch.
    int n = blockIdx.x * blockDim.x + threadIdx.x;

    int b = n / HW;
    int r = n - b * HW;                  // h*W + w within the image

    // flow channel 0 (disparity) for this pixel
    float disp = __ldg(flow + (size_t)b * 2 * HW + r);

    float* outp = out + (size_t)b * C * HW + r;

    process_pair(c0 + (size_t)n * 256, 256, disp,
                 c1 + (size_t)n * 128, 128, disp * 0.5f,
                 outp);
    process_pair(c2 + (size_t)n * 64,  64,  disp * 0.25f,
                 c3 + (size_t)n * 32,  32,  disp * 0.125f,
                 outp + 2 * K * HW);
}

} // namespace

extern "C" void kernel_launch(void* const* d_in, const int* in_sizes, int n_in,
                              void* d_out, int out_size)
{
    const float* c0   = (const float*)d_in[0];
    const float* c1   = (const float*)d_in[1];
    const float* c2   = (const float*)d_in[2];
    const float* c3   = (const float*)d_in[3];
    const float* flow = (const float*)d_in[4];
    float* out = (float*)d_out;

    constexpr int TPB = 64;
    int blocks = N / TPB;               // 3072, exact
    corr_lookup_kernel<<<blocks, TPB>>>(c0, c1, c2, c3, flow, out);
}